// round 1
// baseline (speedup 1.0000x reference)
#include <cuda_runtime.h>
#include <math.h>

// Problem constants
#define NB   8
#define TT   1024
#define EE   1024
#define DD   1025
#define NH   16
#define HDm  64
#define BHn  (NB*NH)      // 128
#define MM   (NB*TT)      // 8192
#define EPSF 1e-8f
#define ATT_SCALE 0.125f  // hd^-0.5

// Scratch (allocated at module load; no runtime allocation)
__device__ float g_y[3][(size_t)MM*DD];             // linear outputs (q,k,v / final reuses [0])
__device__ float g_qkv[3][(size_t)BHn*TT*(HDm+1)];  // head-shaped q,k,v  [bh][t][65]
__device__ float g_ao[(size_t)MM*DD];               // attention output + global time

// ---------------------------------------------------------------------------
// GEMM: Y[m,n] = sum_d X[m,d]*W[n,d] + b[n].  X:[MM,DD], W:[DD,DD] row-major.
// 128x128 tile, BK=8, 256 threads, 8x8 microtile.
// ---------------------------------------------------------------------------
__global__ __launch_bounds__(256) void sgemm_k(
    const float* __restrict__ Xext,
    const float* __restrict__ W0, const float* __restrict__ B0,
    const float* __restrict__ W1, const float* __restrict__ B1,
    const float* __restrict__ W2, const float* __restrict__ B2)
{
    const int w = blockIdx.z;
    const float* X  = Xext ? Xext : g_ao;
    const float* Wp = (w==0) ? W0 : ((w==1) ? W1 : W2);
    const float* Bp = (w==0) ? B0 : ((w==1) ? B1 : B2);
    float* Y = g_y[w];

    __shared__ float As[8][132];
    __shared__ float Bs[8][132];

    const int t  = threadIdx.x;
    const int tx = t & 15, ty = t >> 4;
    const int bm = blockIdx.y << 7, bn = blockIdx.x << 7;
    const int r  = t >> 1, cb = (t & 1) << 2;

    float acc[8][8];
    #pragma unroll
    for (int i = 0; i < 8; i++)
        #pragma unroll
        for (int j = 0; j < 8; j++) acc[i][j] = 0.f;

    const int nB = bn + r;
    const float* xrow = X + (size_t)(bm + r) * DD;
    const float* wrow = Wp + (size_t)((nB < DD) ? nB : 0) * DD;
    const bool nok = (nB < DD);

    for (int k0 = 0; k0 < DD; k0 += 8) {
        #pragma unroll
        for (int i = 0; i < 4; i++) {
            int k = k0 + cb + i;
            bool kok = (k < DD);
            As[cb+i][r] = kok ? xrow[k] : 0.f;
            Bs[cb+i][r] = (kok && nok) ? wrow[k] : 0.f;
        }
        __syncthreads();
        #pragma unroll
        for (int kk = 0; kk < 8; kk++) {
            float a[8], b[8];
            #pragma unroll
            for (int i = 0; i < 8; i++) a[i] = As[kk][(ty<<3)+i];
            #pragma unroll
            for (int j = 0; j < 8; j++) b[j] = Bs[kk][(tx<<3)+j];
            #pragma unroll
            for (int i = 0; i < 8; i++)
                #pragma unroll
                for (int j = 0; j < 8; j++) acc[i][j] = fmaf(a[i], b[j], acc[i][j]);
        }
        __syncthreads();
    }

    #pragma unroll
    for (int i = 0; i < 8; i++) {
        int m = bm + (ty<<3) + i;
        float* yr = Y + (size_t)m * DD;
        #pragma unroll
        for (int j = 0; j < 8; j++) {
            int n = bn + (tx<<3) + j;
            if (n < DD) yr[n] = acc[i][j] + Bp[n];
        }
    }
}

// ---------------------------------------------------------------------------
// Lorentz transform + head-shaping for q/k/v.
// Per row: time=sigmoid(y0)*exp(ls)+1.1, scale=(time^2-1)/max(sum sq, eps),
// per head h: time_h = sqrt(scale*sum_h + 1), space_h = sqrt(scale)*y_space_h
// Writes g_qkv[w][b*H+h][t][0..64].
// ---------------------------------------------------------------------------
__global__ __launch_bounds__(256) void transform_qkv_k(
    const float* __restrict__ lsq, const float* __restrict__ lsk,
    const float* __restrict__ lsv)
{
    const int m = blockIdx.x, w = blockIdx.y;
    const float* y = g_y[w] + (size_t)m * DD;
    __shared__ float sh[EE];
    __shared__ float hs[NH];
    __shared__ float bc[2];
    const int t = threadIdx.x;

    float v[4];
    #pragma unroll
    for (int i = 0; i < 4; i++) {
        int j = t + (i << 8);
        v[i] = y[1 + j];
        sh[j] = v[i] * v[i];
    }
    __syncthreads();
    if (t < NH) {
        float s = 0.f;
        for (int j = 0; j < HDm; j++) s += sh[t*HDm + ((j + t) & 63)];
        hs[t] = s;
    }
    __syncthreads();
    if (t == 0) {
        float s2 = 0.f;
        #pragma unroll
        for (int h = 0; h < NH; h++) s2 += hs[h];
        float ls = (w==0) ? lsq[0] : ((w==1) ? lsk[0] : lsv[0]);
        float y0 = y[0];
        float time = expf(ls) / (1.f + expf(-y0)) + 1.1f;
        float sc = (time*time - 1.f) / fmaxf(s2, EPSF);
        bc[0] = sc;
        bc[1] = sqrtf(sc);
    }
    __syncthreads();
    const float sc = bc[0], ss = bc[1];
    const int b = m >> 10, tt = m & 1023;
    float* base = g_qkv[w];
    #pragma unroll
    for (int i = 0; i < 4; i++) {
        int j = t + (i << 8);
        int h = j >> 6, d = j & 63;
        base[((size_t)(b*NH + h)*TT + tt)*(HDm+1) + 1 + d] = ss * v[i];
    }
    if (t < NH)
        base[((size_t)(b*NH + t)*TT + tt)*(HDm+1)] = sqrtf(sc * hs[t] + 1.f);
}

// ---------------------------------------------------------------------------
// Flash attention + Lorentz centroid, fused.
// grid (T/64, BH), 256 threads; 64 q-rows/block, 64-key tiles, online softmax.
// score = 0.25*linner + 0.25 + bias; linner uses k_time negated.
// Epilogue: centroid normalize; writes space dims into g_ao[b][t][1+h*64+d].
// ---------------------------------------------------------------------------
__global__ __launch_bounds__(256) void attn_k(const float* __restrict__ bias_p)
{
    extern __shared__ float smv[];
    float* Qs  = smv;             // 64*65
    float* Ks  = Qs  + 64*65;     // 64*65 (time negated at col 0)
    float* Vsp = Ks  + 64*65;     // 64*64 space
    float* Vst = Vsp + 64*64;     // 64 time
    float* Ss  = Vst + 64;        // 64*65 (prob tile, pitch 65)
    float* pm  = Ss  + 64*65;     // 64*16 max partials
    float* ps  = pm  + 64*16;     // 64*16 sum partials
    float* mrow= ps  + 64*16;     // 64
    float* lrow= mrow + 64;
    float* arow= lrow + 64;
    float* otm = arow + 64;       // accumulated time column

    const int t  = threadIdx.x;
    const int tx = t & 15, ty = t >> 4;
    const int bh = blockIdx.y;
    const int qb = blockIdx.x << 6;
    const float sc1 = 2.f * ATT_SCALE;                 // 0.25
    const float sc0 = 2.f * ATT_SCALE + bias_p[0];     // 0.25 + bias

    const float* Qg = g_qkv[0] + (size_t)bh * TT * 65;
    const float* Kg = g_qkv[1] + (size_t)bh * TT * 65;
    const float* Vg = g_qkv[2] + (size_t)bh * TT * 65;

    for (int idx = t; idx < 64*65; idx += 256) {
        int r = idx / 65, c = idx - r*65;
        Qs[r*65 + c] = Qg[(size_t)(qb + r)*65 + c];
    }
    if (t < 64) { mrow[t] = -INFINITY; lrow[t] = 0.f; otm[t] = 0.f; }

    float o[4][4];
    #pragma unroll
    for (int i = 0; i < 4; i++)
        #pragma unroll
        for (int j = 0; j < 4; j++) o[i][j] = 0.f;
    __syncthreads();

    for (int kb = 0; kb < TT; kb += 64) {
        // load K (negate time), V (split time/space)
        for (int idx = t; idx < 64*65; idx += 256) {
            int r = idx / 65, c = idx - r*65;
            float kv = Kg[(size_t)(kb + r)*65 + c];
            Ks[r*65 + c] = (c == 0) ? -kv : kv;
            float vv = Vg[(size_t)(kb + r)*65 + c];
            if (c == 0) Vst[r] = vv; else Vsp[r*64 + (c-1)] = vv;
        }
        __syncthreads();

        // S = QK^T fragment
        float sf[4][4];
        #pragma unroll
        for (int i = 0; i < 4; i++)
            #pragma unroll
            for (int j = 0; j < 4; j++) sf[i][j] = 0.f;
        for (int d = 0; d < 65; d++) {
            float a[4], b[4];
            #pragma unroll
            for (int i = 0; i < 4; i++) a[i] = Qs[((ty<<2)+i)*65 + d];
            #pragma unroll
            for (int j = 0; j < 4; j++) b[j] = Ks[((tx<<2)+j)*65 + d];
            #pragma unroll
            for (int i = 0; i < 4; i++)
                #pragma unroll
                for (int j = 0; j < 4; j++) sf[i][j] = fmaf(a[i], b[j], sf[i][j]);
        }
        #pragma unroll
        for (int i = 0; i < 4; i++) {
            float mx = -INFINITY;
            #pragma unroll
            for (int j = 0; j < 4; j++) {
                sf[i][j] = fmaf(sf[i][j], sc1, sc0);
                mx = fmaxf(mx, sf[i][j]);
            }
            pm[((ty<<2)+i)*16 + tx] = mx;
        }
        __syncthreads();

        if (t < 64) {
            float mold = mrow[t], mn = mold;
            #pragma unroll
            for (int x = 0; x < 16; x++) mn = fmaxf(mn, pm[t*16 + x]);
            float al = __expf(mold - mn);
            mrow[t] = mn; arow[t] = al;
            lrow[t] *= al; otm[t] *= al;
        }
        __syncthreads();

        // exp, write P, partial sums, rescale O
        #pragma unroll
        for (int i = 0; i < 4; i++) {
            int gi = (ty<<2) + i;
            float ml = mrow[gi], al = arow[gi];
            float psl = 0.f;
            #pragma unroll
            for (int j = 0; j < 4; j++) {
                float p = __expf(sf[i][j] - ml);
                Ss[gi*65 + (tx<<2) + j] = p;
                psl += p;
                o[i][j] *= al;
            }
            ps[gi*16 + tx] = psl;
        }
        __syncthreads();

        if (t < 64) {
            float s = 0.f;
            #pragma unroll
            for (int x = 0; x < 16; x++) s += ps[t*16 + x];
            lrow[t] += s;
            float ot = 0.f;
            for (int j = 0; j < 64; j++) ot = fmaf(Ss[t*65 + j], Vst[j], ot);
            otm[t] += ot;
        }

        // O += P @ V_space
        for (int j = 0; j < 64; j++) {
            float pv[4];
            #pragma unroll
            for (int i = 0; i < 4; i++) pv[i] = Ss[((ty<<2)+i)*65 + j];
            float4 vv = *(const float4*)&Vsp[j*64 + (tx<<2)];
            #pragma unroll
            for (int i = 0; i < 4; i++) {
                o[i][0] = fmaf(pv[i], vv.x, o[i][0]);
                o[i][1] = fmaf(pv[i], vv.y, o[i][1]);
                o[i][2] = fmaf(pv[i], vv.z, o[i][2]);
                o[i][3] = fmaf(pv[i], vv.w, o[i][3]);
            }
        }
        __syncthreads();
    }

    // Epilogue: probs-normalize, centroid normalize, write space dims.
    #pragma unroll
    for (int i = 0; i < 4; i++) {
        int gi = (ty<<2) + i;
        float li = 1.f / lrow[gi];
        float ssq = 0.f;
        #pragma unroll
        for (int j = 0; j < 4; j++) {
            o[i][j] *= li;
            ssq = fmaf(o[i][j], o[i][j], ssq);
        }
        ps[gi*16 + tx] = ssq;
    }
    __syncthreads();
    if (t < 64) {
        float s = 0.f;
        #pragma unroll
        for (int x = 0; x < 16; x++) s += ps[t*16 + x];
        float tav = otm[t] / lrow[t];
        float ni = tav*tav - s;
        arow[t] = 1.f / sqrtf(fmaxf(fabsf(ni), EPSF));
    }
    __syncthreads();

    const int b = bh >> 4, h = bh & 15;
    #pragma unroll
    for (int i = 0; i < 4; i++) {
        int gi = (ty<<2) + i;
        float dv = arow[gi];
        float* dst = g_ao + ((size_t)(b*TT) + qb + gi)*DD + 1 + h*64 + (tx<<2);
        #pragma unroll
        for (int j = 0; j < 4; j++) dst[j] = o[i][j] * dv;
    }
}

// ---------------------------------------------------------------------------
// Global add_time for attention output rows: ao[m][0] = sqrt(1 + sum space^2)
// ---------------------------------------------------------------------------
__global__ __launch_bounds__(256) void ao_time_k()
{
    const int m = blockIdx.x;
    float* row = g_ao + (size_t)m * DD;
    __shared__ float red[256];
    const int t = threadIdx.x;
    float s = 0.f;
    #pragma unroll
    for (int i = 0; i < 4; i++) {
        float x = row[1 + t + (i << 8)];
        s = fmaf(x, x, s);
    }
    red[t] = s;
    __syncthreads();
    for (int o2 = 128; o2 > 0; o2 >>= 1) {
        if (t < o2) red[t] += red[t + o2];
        __syncthreads();
    }
    if (t == 0) row[0] = sqrtf(red[0] + 1.f);
}

// ---------------------------------------------------------------------------
// Final Lorentz transform (no head shaping): out row = [time, ss*y_space]
// ---------------------------------------------------------------------------
__global__ __launch_bounds__(256) void transform_final_k(
    const float* __restrict__ lso, float* __restrict__ out)
{
    const int m = blockIdx.x;
    const float* y = g_y[0] + (size_t)m * DD;
    __shared__ float red[256];
    __shared__ float bc[2];
    const int t = threadIdx.x;
    float v[4]; float s = 0.f;
    #pragma unroll
    for (int i = 0; i < 4; i++) {
        v[i] = y[1 + t + (i << 8)];
        s = fmaf(v[i], v[i], s);
    }
    red[t] = s;
    __syncthreads();
    for (int o2 = 128; o2 > 0; o2 >>= 1) {
        if (t < o2) red[t] += red[t + o2];
        __syncthreads();
    }
    if (t == 0) {
        float time = expf(lso[0]) / (1.f + expf(-y[0])) + 1.1f;
        float sc = (time*time - 1.f) / fmaxf(red[0], EPSF);
        bc[0] = time;
        bc[1] = sqrtf(sc);
    }
    __syncthreads();
    const float ss = bc[1];
    float* orow = out + (size_t)m * DD;
    if (t == 0) orow[0] = bc[0];
    #pragma unroll
    for (int i = 0; i < 4; i++) orow[1 + t + (i << 8)] = ss * v[i];
}

// ---------------------------------------------------------------------------
extern "C" void kernel_launch(void* const* d_in, const int* in_sizes, int n_in,
                              void* d_out, int out_size)
{
    const float* hid = (const float*)d_in[0];
    const float* Wq  = (const float*)d_in[1];
    const float* bq  = (const float*)d_in[2];
    const float* sq  = (const float*)d_in[3];
    const float* Wk  = (const float*)d_in[4];
    const float* bk  = (const float*)d_in[5];
    const float* sk  = (const float*)d_in[6];
    const float* Wv  = (const float*)d_in[7];
    const float* bv  = (const float*)d_in[8];
    const float* sv  = (const float*)d_in[9];
    const float* Wo  = (const float*)d_in[10];
    const float* bo  = (const float*)d_in[11];
    const float* so  = (const float*)d_in[12];
    const float* ab  = (const float*)d_in[13];
    float* out = (float*)d_out;

    static const size_t attn_smem = (size_t)(2*64*65 + 64*64 + 64 + 64*65 + 2*64*16 + 4*64) * sizeof(float);
    cudaFuncSetAttribute(attn_k, cudaFuncAttributeMaxDynamicSharedMemorySize, (int)attn_smem);

    // q/k/v linear projections (z-batched GEMM)
    sgemm_k<<<dim3(9, 64, 3), 256>>>(hid, Wq, bq, Wk, bk, Wv, bv);
    // Lorentz transform + head shaping
    transform_qkv_k<<<dim3(MM, 3), 256>>>(sq, sk, sv);
    // flash attention + centroid
    attn_k<<<dim3(TT/64, BHn), 256, attn_smem>>>(ab);
    // global time column for attention output
    ao_time_k<<<MM, 256>>>();
    // output projection
    sgemm_k<<<dim3(9, 64, 1), 256>>>(nullptr, Wo, bo, Wo, bo, Wo, bo);
    // final Lorentz transform -> d_out
    transform_final_k<<<MM, 256>>>(so, out);
}

// round 2
// speedup vs baseline: 1.5570x; 1.5570x over previous
#include <cuda_runtime.h>
#include <math.h>

// Problem constants
#define NB   8
#define TT   1024
#define EE   1024
#define DD   1025
#define NH   16
#define HDm  64
#define BHn  (NB*NH)      // 128
#define MM   (NB*TT)      // 8192
#define EPSF 1e-8f
#define ATT_SCALE 0.125f  // hd^-0.5

// Scratch (module-scope; no runtime allocation)
__device__ float g_y[3][(size_t)MM*DD];             // linear outputs (q,k,v / final reuses [0])
__device__ float g_qkv[3][(size_t)BHn*TT*(HDm+1)];  // head-shaped q,k,v  [bh][t][65]
__device__ float g_ao[(size_t)MM*DD];               // attention output + global time

__device__ __forceinline__ unsigned f2tf(float x) {
    unsigned u; asm("cvt.rna.tf32.f32 %0, %1;" : "=r"(u) : "f"(x)); return u;
}

// ---------------------------------------------------------------------------
// TF32 tensor-core GEMM: Y[m,n] = sum_d X[m,d]*W[n,d] + b[n]
// X:[MM,DD] row-major, W:[DD,DD] row-major (so W is "col" operand k-major).
// Block 128x128xBK16, 256 threads = 8 warps, warp tile 64x32 via m16n8k8.
// Smem m-major with pitch 20 words: STS.128 staging is 16B-aligned and the
// fragment LDS pattern (rows base+g, cols tg / tg+4) is bank-conflict-free.
// ---------------------------------------------------------------------------
#define GP 20   // smem pitch (words)

__global__ __launch_bounds__(256, 2) void gemm_tf32_k(
    const float* __restrict__ Xext,
    const float* __restrict__ W0, const float* __restrict__ B0,
    const float* __restrict__ W1, const float* __restrict__ B1,
    const float* __restrict__ W2, const float* __restrict__ B2)
{
    const int w = blockIdx.z;
    const float* X  = Xext ? Xext : g_ao;
    const float* Wp = (w==0) ? W0 : ((w==1) ? W1 : W2);
    const float* Bp = (w==0) ? B0 : ((w==1) ? B1 : B2);
    float* Y = g_y[w];

    __shared__ unsigned As[128][GP];   // [m][k]
    __shared__ unsigned Bs[128][GP];   // [n][k]

    const int t    = threadIdx.x;
    const int lane = t & 31;
    const int warp = t >> 5;
    const int g    = lane >> 2;        // 0..7
    const int tg   = lane & 3;         // 0..3
    const int wm   = (warp & 1) << 6;  // 0 / 64
    const int wn   = (warp >> 1) << 5; // 0 / 32 / 64 / 96
    const int bm   = blockIdx.y << 7;
    const int bn   = blockIdx.x << 7;

    // staging coords: thread covers rows sr, sr+64 at cols sc..sc+3
    const int sr = t >> 2;             // 0..63
    const int sc = (t & 3) << 2;       // 0,4,8,12

    const float* xr0 = X + (size_t)(bm + sr) * DD;
    const float* xr1 = X + (size_t)(bm + sr + 64) * DD;
    const int n0 = bn + sr, n1 = bn + sr + 64;
    const bool n0ok = (n0 < DD), n1ok = (n1 < DD);
    const float* wr0 = Wp + (size_t)(n0ok ? n0 : 0) * DD;
    const float* wr1 = Wp + (size_t)(n1ok ? n1 : 0) * DD;

    float acc[4][4][4];
    #pragma unroll
    for (int i = 0; i < 4; i++)
        #pragma unroll
        for (int j = 0; j < 4; j++)
            #pragma unroll
            for (int r = 0; r < 4; r++) acc[i][j][r] = 0.f;

    float rA[8], rB[8];
    // prologue: k0 = 0 (cols 0..15 all valid)
    #pragma unroll
    for (int i = 0; i < 4; i++) {
        rA[i]   = xr0[sc + i];
        rA[4+i] = xr1[sc + i];
        rB[i]   = n0ok ? wr0[sc + i] : 0.f;
        rB[4+i] = n1ok ? wr1[sc + i] : 0.f;
    }

    for (int k0 = 0; k0 < DD; k0 += 16) {
        // stage current tile (vectorized, tf32-converted)
        *(uint4*)&As[sr][sc]      = make_uint4(f2tf(rA[0]), f2tf(rA[1]), f2tf(rA[2]), f2tf(rA[3]));
        *(uint4*)&As[sr + 64][sc] = make_uint4(f2tf(rA[4]), f2tf(rA[5]), f2tf(rA[6]), f2tf(rA[7]));
        *(uint4*)&Bs[sr][sc]      = make_uint4(f2tf(rB[0]), f2tf(rB[1]), f2tf(rB[2]), f2tf(rB[3]));
        *(uint4*)&Bs[sr + 64][sc] = make_uint4(f2tf(rB[4]), f2tf(rB[5]), f2tf(rB[6]), f2tf(rB[7]));
        __syncthreads();

        // prefetch next tile into registers (overlaps with compute)
        const int kn = k0 + 16;
        if (kn < DD) {
            #pragma unroll
            for (int i = 0; i < 4; i++) {
                int k = kn + sc + i;
                bool kok = (k < DD);
                rA[i]   = kok ? xr0[k] : 0.f;
                rA[4+i] = kok ? xr1[k] : 0.f;
                rB[i]   = (kok && n0ok) ? wr0[k] : 0.f;
                rB[4+i] = (kok && n1ok) ? wr1[k] : 0.f;
            }
        }

        #pragma unroll
        for (int ks = 0; ks < 16; ks += 8) {
            unsigned a[4][4], b[4][2];
            #pragma unroll
            for (int mi = 0; mi < 4; mi++) {
                int row = wm + (mi << 4) + g;
                a[mi][0] = As[row    ][ks + tg];
                a[mi][1] = As[row + 8][ks + tg];
                a[mi][2] = As[row    ][ks + tg + 4];
                a[mi][3] = As[row + 8][ks + tg + 4];
            }
            #pragma unroll
            for (int nj = 0; nj < 4; nj++) {
                int col = wn + (nj << 3) + g;
                b[nj][0] = Bs[col][ks + tg];
                b[nj][1] = Bs[col][ks + tg + 4];
            }
            #pragma unroll
            for (int mi = 0; mi < 4; mi++)
                #pragma unroll
                for (int nj = 0; nj < 4; nj++)
                    asm volatile(
                        "mma.sync.aligned.m16n8k8.row.col.f32.tf32.tf32.f32 "
                        "{%0,%1,%2,%3}, {%4,%5,%6,%7}, {%8,%9}, {%0,%1,%2,%3};"
                        : "+f"(acc[mi][nj][0]), "+f"(acc[mi][nj][1]),
                          "+f"(acc[mi][nj][2]), "+f"(acc[mi][nj][3])
                        : "r"(a[mi][0]), "r"(a[mi][1]), "r"(a[mi][2]), "r"(a[mi][3]),
                          "r"(b[nj][0]), "r"(b[nj][1]));
        }
        __syncthreads();
    }

    // epilogue: c0:(g, 2tg) c1:(g, 2tg+1) c2:(g+8, 2tg) c3:(g+8, 2tg+1)
    #pragma unroll
    for (int mi = 0; mi < 4; mi++) {
        int row = bm + wm + (mi << 4) + g;
        float* yr0 = Y + (size_t)row * DD;
        float* yr1 = Y + (size_t)(row + 8) * DD;
        #pragma unroll
        for (int nj = 0; nj < 4; nj++) {
            int col = bn + wn + (nj << 3) + (tg << 1);
            if (col < DD) {
                float bb = Bp[col];
                yr0[col] = acc[mi][nj][0] + bb;
                yr1[col] = acc[mi][nj][2] + bb;
            }
            if (col + 1 < DD) {
                float bb = Bp[col + 1];
                yr0[col + 1] = acc[mi][nj][1] + bb;
                yr1[col + 1] = acc[mi][nj][3] + bb;
            }
        }
    }
}

// ---------------------------------------------------------------------------
// Lorentz transform + head-shaping for q/k/v.
// ---------------------------------------------------------------------------
__global__ __launch_bounds__(256) void transform_qkv_k(
    const float* __restrict__ lsq, const float* __restrict__ lsk,
    const float* __restrict__ lsv)
{
    const int m = blockIdx.x, w = blockIdx.y;
    const float* y = g_y[w] + (size_t)m * DD;
    __shared__ float sh[EE];
    __shared__ float hs[NH];
    __shared__ float bc[2];
    const int t = threadIdx.x;

    float v[4];
    #pragma unroll
    for (int i = 0; i < 4; i++) {
        int j = t + (i << 8);
        v[i] = y[1 + j];
        sh[j] = v[i] * v[i];
    }
    __syncthreads();
    if (t < NH) {
        float s = 0.f;
        for (int j = 0; j < HDm; j++) s += sh[t*HDm + ((j + t) & 63)];
        hs[t] = s;
    }
    __syncthreads();
    if (t == 0) {
        float s2 = 0.f;
        #pragma unroll
        for (int h = 0; h < NH; h++) s2 += hs[h];
        float ls = (w==0) ? lsq[0] : ((w==1) ? lsk[0] : lsv[0]);
        float y0 = y[0];
        float time = expf(ls) / (1.f + expf(-y0)) + 1.1f;
        float sc = (time*time - 1.f) / fmaxf(s2, EPSF);
        bc[0] = sc;
        bc[1] = sqrtf(sc);
    }
    __syncthreads();
    const float sc = bc[0], ss = bc[1];
    const int b = m >> 10, tt = m & 1023;
    float* base = g_qkv[w];
    #pragma unroll
    for (int i = 0; i < 4; i++) {
        int j = t + (i << 8);
        int h = j >> 6, d = j & 63;
        base[((size_t)(b*NH + h)*TT + tt)*(HDm+1) + 1 + d] = ss * v[i];
    }
    if (t < NH)
        base[((size_t)(b*NH + t)*TT + tt)*(HDm+1)] = sqrtf(sc * hs[t] + 1.f);
}

// ---------------------------------------------------------------------------
// Flash attention + Lorentz centroid, fused (fp32 SIMT).
// ---------------------------------------------------------------------------
__global__ __launch_bounds__(256) void attn_k(const float* __restrict__ bias_p)
{
    extern __shared__ float smv[];
    float* Qs  = smv;             // 64*65
    float* Ks  = Qs  + 64*65;     // 64*65 (time negated at col 0)
    float* Vsp = Ks  + 64*65;     // 64*64 space
    float* Vst = Vsp + 64*64;     // 64 time
    float* Ss  = Vst + 64;        // 64*65 (prob tile, pitch 65)
    float* pm  = Ss  + 64*65;     // 64*16 max partials
    float* ps  = pm  + 64*16;     // 64*16 sum partials
    float* mrow= ps  + 64*16;     // 64
    float* lrow= mrow + 64;
    float* arow= lrow + 64;
    float* otm = arow + 64;       // accumulated time column

    const int t  = threadIdx.x;
    const int tx = t & 15, ty = t >> 4;
    const int bh = blockIdx.y;
    const int qb = blockIdx.x << 6;
    const float sc1 = 2.f * ATT_SCALE;                 // 0.25
    const float sc0 = 2.f * ATT_SCALE + bias_p[0];     // 0.25 + bias

    const float* Qg = g_qkv[0] + (size_t)bh * TT * 65;
    const float* Kg = g_qkv[1] + (size_t)bh * TT * 65;
    const float* Vg = g_qkv[2] + (size_t)bh * TT * 65;

    for (int idx = t; idx < 64*65; idx += 256) {
        int r = idx / 65, c = idx - r*65;
        Qs[r*65 + c] = Qg[(size_t)(qb + r)*65 + c];
    }
    if (t < 64) { mrow[t] = -INFINITY; lrow[t] = 0.f; otm[t] = 0.f; }

    float o[4][4];
    #pragma unroll
    for (int i = 0; i < 4; i++)
        #pragma unroll
        for (int j = 0; j < 4; j++) o[i][j] = 0.f;
    __syncthreads();

    for (int kb = 0; kb < TT; kb += 64) {
        for (int idx = t; idx < 64*65; idx += 256) {
            int r = idx / 65, c = idx - r*65;
            float kv = Kg[(size_t)(kb + r)*65 + c];
            Ks[r*65 + c] = (c == 0) ? -kv : kv;
            float vv = Vg[(size_t)(kb + r)*65 + c];
            if (c == 0) Vst[r] = vv; else Vsp[r*64 + (c-1)] = vv;
        }
        __syncthreads();

        float sf[4][4];
        #pragma unroll
        for (int i = 0; i < 4; i++)
            #pragma unroll
            for (int j = 0; j < 4; j++) sf[i][j] = 0.f;
        for (int d = 0; d < 65; d++) {
            float a[4], b[4];
            #pragma unroll
            for (int i = 0; i < 4; i++) a[i] = Qs[((ty<<2)+i)*65 + d];
            #pragma unroll
            for (int j = 0; j < 4; j++) b[j] = Ks[((tx<<2)+j)*65 + d];
            #pragma unroll
            for (int i = 0; i < 4; i++)
                #pragma unroll
                for (int j = 0; j < 4; j++) sf[i][j] = fmaf(a[i], b[j], sf[i][j]);
        }
        #pragma unroll
        for (int i = 0; i < 4; i++) {
            float mx = -INFINITY;
            #pragma unroll
            for (int j = 0; j < 4; j++) {
                sf[i][j] = fmaf(sf[i][j], sc1, sc0);
                mx = fmaxf(mx, sf[i][j]);
            }
            pm[((ty<<2)+i)*16 + tx] = mx;
        }
        __syncthreads();

        if (t < 64) {
            float mold = mrow[t], mn = mold;
            #pragma unroll
            for (int x = 0; x < 16; x++) mn = fmaxf(mn, pm[t*16 + x]);
            float al = __expf(mold - mn);
            mrow[t] = mn; arow[t] = al;
            lrow[t] *= al; otm[t] *= al;
        }
        __syncthreads();

        #pragma unroll
        for (int i = 0; i < 4; i++) {
            int gi = (ty<<2) + i;
            float ml = mrow[gi], al = arow[gi];
            float psl = 0.f;
            #pragma unroll
            for (int j = 0; j < 4; j++) {
                float p = __expf(sf[i][j] - ml);
                Ss[gi*65 + (tx<<2) + j] = p;
                psl += p;
                o[i][j] *= al;
            }
            ps[gi*16 + tx] = psl;
        }
        __syncthreads();

        if (t < 64) {
            float s = 0.f;
            #pragma unroll
            for (int x = 0; x < 16; x++) s += ps[t*16 + x];
            lrow[t] += s;
            float ot = 0.f;
            for (int j = 0; j < 64; j++) ot = fmaf(Ss[t*65 + j], Vst[j], ot);
            otm[t] += ot;
        }

        for (int j = 0; j < 64; j++) {
            float pv[4];
            #pragma unroll
            for (int i = 0; i < 4; i++) pv[i] = Ss[((ty<<2)+i)*65 + j];
            float4 vv = *(const float4*)&Vsp[j*64 + (tx<<2)];
            #pragma unroll
            for (int i = 0; i < 4; i++) {
                o[i][0] = fmaf(pv[i], vv.x, o[i][0]);
                o[i][1] = fmaf(pv[i], vv.y, o[i][1]);
                o[i][2] = fmaf(pv[i], vv.z, o[i][2]);
                o[i][3] = fmaf(pv[i], vv.w, o[i][3]);
            }
        }
        __syncthreads();
    }

    #pragma unroll
    for (int i = 0; i < 4; i++) {
        int gi = (ty<<2) + i;
        float li = 1.f / lrow[gi];
        float ssq = 0.f;
        #pragma unroll
        for (int j = 0; j < 4; j++) {
            o[i][j] *= li;
            ssq = fmaf(o[i][j], o[i][j], ssq);
        }
        ps[gi*16 + tx] = ssq;
    }
    __syncthreads();
    if (t < 64) {
        float s = 0.f;
        #pragma unroll
        for (int x = 0; x < 16; x++) s += ps[t*16 + x];
        float tav = otm[t] / lrow[t];
        float ni = tav*tav - s;
        arow[t] = 1.f / sqrtf(fmaxf(fabsf(ni), EPSF));
    }
    __syncthreads();

    const int b = bh >> 4, h = bh & 15;
    #pragma unroll
    for (int i = 0; i < 4; i++) {
        int gi = (ty<<2) + i;
        float dv = arow[gi];
        float* dst = g_ao + ((size_t)(b*TT) + qb + gi)*DD + 1 + h*64 + (tx<<2);
        #pragma unroll
        for (int j = 0; j < 4; j++) dst[j] = o[i][j] * dv;
    }
}

// ---------------------------------------------------------------------------
// Global add_time for attention output rows
// ---------------------------------------------------------------------------
__global__ __launch_bounds__(256) void ao_time_k()
{
    const int m = blockIdx.x;
    float* row = g_ao + (size_t)m * DD;
    __shared__ float red[256];
    const int t = threadIdx.x;
    float s = 0.f;
    #pragma unroll
    for (int i = 0; i < 4; i++) {
        float x = row[1 + t + (i << 8)];
        s = fmaf(x, x, s);
    }
    red[t] = s;
    __syncthreads();
    for (int o2 = 128; o2 > 0; o2 >>= 1) {
        if (t < o2) red[t] += red[t + o2];
        __syncthreads();
    }
    if (t == 0) row[0] = sqrtf(red[0] + 1.f);
}

// ---------------------------------------------------------------------------
// Final Lorentz transform -> out
// ---------------------------------------------------------------------------
__global__ __launch_bounds__(256) void transform_final_k(
    const float* __restrict__ lso, float* __restrict__ out)
{
    const int m = blockIdx.x;
    const float* y = g_y[0] + (size_t)m * DD;
    __shared__ float red[256];
    __shared__ float bc[2];
    const int t = threadIdx.x;
    float v[4]; float s = 0.f;
    #pragma unroll
    for (int i = 0; i < 4; i++) {
        v[i] = y[1 + t + (i << 8)];
        s = fmaf(v[i], v[i], s);
    }
    red[t] = s;
    __syncthreads();
    for (int o2 = 128; o2 > 0; o2 >>= 1) {
        if (t < o2) red[t] += red[t + o2];
        __syncthreads();
    }
    if (t == 0) {
        float time = expf(lso[0]) / (1.f + expf(-y[0])) + 1.1f;
        float sc = (time*time - 1.f) / fmaxf(red[0], EPSF);
        bc[0] = time;
        bc[1] = sqrtf(sc);
    }
    __syncthreads();
    const float ss = bc[1];
    float* orow = out + (size_t)m * DD;
    if (t == 0) orow[0] = bc[0];
    #pragma unroll
    for (int i = 0; i < 4; i++) orow[1 + t + (i << 8)] = ss * v[i];
}

// ---------------------------------------------------------------------------
extern "C" void kernel_launch(void* const* d_in, const int* in_sizes, int n_in,
                              void* d_out, int out_size)
{
    const float* hid = (const float*)d_in[0];
    const float* Wq  = (const float*)d_in[1];
    const float* bq  = (const float*)d_in[2];
    const float* sq  = (const float*)d_in[3];
    const float* Wk  = (const float*)d_in[4];
    const float* bk  = (const float*)d_in[5];
    const float* sk  = (const float*)d_in[6];
    const float* Wv  = (const float*)d_in[7];
    const float* bv  = (const float*)d_in[8];
    const float* sv  = (const float*)d_in[9];
    const float* Wo  = (const float*)d_in[10];
    const float* bo  = (const float*)d_in[11];
    const float* so  = (const float*)d_in[12];
    const float* ab  = (const float*)d_in[13];
    float* out = (float*)d_out;

    static const size_t attn_smem = (size_t)(2*64*65 + 64*64 + 64 + 64*65 + 2*64*16 + 4*64) * sizeof(float);
    cudaFuncSetAttribute(attn_k, cudaFuncAttributeMaxDynamicSharedMemorySize, (int)attn_smem);

    // q/k/v linear projections (z-batched, tf32 tensor cores)
    gemm_tf32_k<<<dim3(9, 64, 3), 256>>>(hid, Wq, bq, Wk, bk, Wv, bv);
    // Lorentz transform + head shaping
    transform_qkv_k<<<dim3(MM, 3), 256>>>(sq, sk, sv);
    // flash attention + centroid
    attn_k<<<dim3(TT/64, BHn), 256, attn_smem>>>(ab);
    // global time column for attention output
    ao_time_k<<<MM, 256>>>();
    // output projection
    gemm_tf32_k<<<dim3(9, 64, 1), 256>>>(nullptr, Wo, bo, Wo, bo, Wo, bo);
    // final Lorentz transform -> d_out
    transform_final_k<<<MM, 256>>>(so, out);
}

// round 6
// speedup vs baseline: 1.6049x; 1.0308x over previous
#include <cuda_runtime.h>
#include <math.h>

// Problem constants
#define NB   8
#define TT   1024
#define EE   1024
#define DD   1025
#define NH   16
#define HDm  64
#define BHn  (NB*NH)      // 128
#define MM   (NB*TT)      // 8192
#define EPSF 1e-8f
#define ATT_SCALE 0.125f  // hd^-0.5

// Scratch (module-scope; no runtime allocation)
__device__ float g_y[3][(size_t)MM*DD];             // linear outputs
__device__ float g_qkv[3][(size_t)BHn*TT*(HDm+1)];  // head-shaped q,k,v [bh][t][65]
__device__ float g_ao[(size_t)MM*DD];               // attention output + global time

__device__ __forceinline__ unsigned f2tf(float x) {
    unsigned u; asm("cvt.rna.tf32.f32 %0, %1;" : "=r"(u) : "f"(x)); return u;
}

#define MMA_TF32(d0,d1,d2,d3,a0,a1,a2,a3,b0,b1) \
    asm volatile("mma.sync.aligned.m16n8k8.row.col.f32.tf32.tf32.f32 " \
        "{%0,%1,%2,%3}, {%4,%5,%6,%7}, {%8,%9}, {%0,%1,%2,%3};" \
        : "+f"(d0), "+f"(d1), "+f"(d2), "+f"(d3) \
        : "r"(a0), "r"(a1), "r"(a2), "r"(a3), "r"(b0), "r"(b1))

// ---------------------------------------------------------------------------
// TF32 tensor-core GEMM: Y = X W^T + b
// ---------------------------------------------------------------------------
#define GP 20

__global__ __launch_bounds__(256, 2) void gemm_tf32_k(
    const float* __restrict__ Xext,
    const float* __restrict__ W0, const float* __restrict__ B0,
    const float* __restrict__ W1, const float* __restrict__ B1,
    const float* __restrict__ W2, const float* __restrict__ B2)
{
    const int w = blockIdx.z;
    const float* X  = Xext ? Xext : g_ao;
    const float* Wp = (w==0) ? W0 : ((w==1) ? W1 : W2);
    const float* Bp = (w==0) ? B0 : ((w==1) ? B1 : B2);
    float* Y = g_y[w];

    __shared__ unsigned As[128][GP];
    __shared__ unsigned Bs[128][GP];

    const int t    = threadIdx.x;
    const int lane = t & 31;
    const int warp = t >> 5;
    const int g    = lane >> 2;
    const int tg   = lane & 3;
    const int wm   = (warp & 1) << 6;
    const int wn   = (warp >> 1) << 5;
    const int bm   = blockIdx.y << 7;
    const int bn   = blockIdx.x << 7;

    const int sr = t >> 2;
    const int sc = (t & 3) << 2;

    const float* xr0 = X + (size_t)(bm + sr) * DD;
    const float* xr1 = X + (size_t)(bm + sr + 64) * DD;
    const int n0 = bn + sr, n1 = bn + sr + 64;
    const bool n0ok = (n0 < DD), n1ok = (n1 < DD);
    const float* wr0 = Wp + (size_t)(n0ok ? n0 : 0) * DD;
    const float* wr1 = Wp + (size_t)(n1ok ? n1 : 0) * DD;

    float acc[4][4][4];
    #pragma unroll
    for (int i = 0; i < 4; i++)
        #pragma unroll
        for (int j = 0; j < 4; j++)
            #pragma unroll
            for (int r = 0; r < 4; r++) acc[i][j][r] = 0.f;

    float rA[8], rB[8];
    #pragma unroll
    for (int i = 0; i < 4; i++) {
        rA[i]   = xr0[sc + i];
        rA[4+i] = xr1[sc + i];
        rB[i]   = n0ok ? wr0[sc + i] : 0.f;
        rB[4+i] = n1ok ? wr1[sc + i] : 0.f;
    }

    for (int k0 = 0; k0 < DD; k0 += 16) {
        *(uint4*)&As[sr][sc]      = make_uint4(f2tf(rA[0]), f2tf(rA[1]), f2tf(rA[2]), f2tf(rA[3]));
        *(uint4*)&As[sr + 64][sc] = make_uint4(f2tf(rA[4]), f2tf(rA[5]), f2tf(rA[6]), f2tf(rA[7]));
        *(uint4*)&Bs[sr][sc]      = make_uint4(f2tf(rB[0]), f2tf(rB[1]), f2tf(rB[2]), f2tf(rB[3]));
        *(uint4*)&Bs[sr + 64][sc] = make_uint4(f2tf(rB[4]), f2tf(rB[5]), f2tf(rB[6]), f2tf(rB[7]));
        __syncthreads();

        const int kn = k0 + 16;
        if (kn < DD) {
            #pragma unroll
            for (int i = 0; i < 4; i++) {
                int k = kn + sc + i;
                bool kok = (k < DD);
                rA[i]   = kok ? xr0[k] : 0.f;
                rA[4+i] = kok ? xr1[k] : 0.f;
                rB[i]   = (kok && n0ok) ? wr0[k] : 0.f;
                rB[4+i] = (kok && n1ok) ? wr1[k] : 0.f;
            }
        }

        #pragma unroll
        for (int ks = 0; ks < 16; ks += 8) {
            unsigned a[4][4], b[4][2];
            #pragma unroll
            for (int mi = 0; mi < 4; mi++) {
                int row = wm + (mi << 4) + g;
                a[mi][0] = As[row    ][ks + tg];
                a[mi][1] = As[row + 8][ks + tg];
                a[mi][2] = As[row    ][ks + tg + 4];
                a[mi][3] = As[row + 8][ks + tg + 4];
            }
            #pragma unroll
            for (int nj = 0; nj < 4; nj++) {
                int col = wn + (nj << 3) + g;
                b[nj][0] = Bs[col][ks + tg];
                b[nj][1] = Bs[col][ks + tg + 4];
            }
            #pragma unroll
            for (int mi = 0; mi < 4; mi++)
                #pragma unroll
                for (int nj = 0; nj < 4; nj++)
                    MMA_TF32(acc[mi][nj][0], acc[mi][nj][1], acc[mi][nj][2], acc[mi][nj][3],
                             a[mi][0], a[mi][1], a[mi][2], a[mi][3], b[nj][0], b[nj][1]);
        }
        __syncthreads();
    }

    #pragma unroll
    for (int mi = 0; mi < 4; mi++) {
        int row = bm + wm + (mi << 4) + g;
        float* yr0 = Y + (size_t)row * DD;
        float* yr1 = Y + (size_t)(row + 8) * DD;
        #pragma unroll
        for (int nj = 0; nj < 4; nj++) {
            int col = bn + wn + (nj << 3) + (tg << 1);
            if (col < DD) {
                float bb = Bp[col];
                yr0[col] = acc[mi][nj][0] + bb;
                yr1[col] = acc[mi][nj][2] + bb;
            }
            if (col + 1 < DD) {
                float bb = Bp[col + 1];
                yr0[col + 1] = acc[mi][nj][1] + bb;
                yr1[col + 1] = acc[mi][nj][3] + bb;
            }
        }
    }
}

// ---------------------------------------------------------------------------
// Lorentz transform + head-shaping for q/k/v.
// ---------------------------------------------------------------------------
__global__ __launch_bounds__(256) void transform_qkv_k(
    const float* __restrict__ lsq, const float* __restrict__ lsk,
    const float* __restrict__ lsv)
{
    const int m = blockIdx.x, w = blockIdx.y;
    const float* y = g_y[w] + (size_t)m * DD;
    __shared__ float sh[EE];
    __shared__ float hs[NH];
    __shared__ float bc[2];
    const int t = threadIdx.x;

    float v[4];
    #pragma unroll
    for (int i = 0; i < 4; i++) {
        int j = t + (i << 8);
        v[i] = y[1 + j];
        sh[j] = v[i] * v[i];
    }
    __syncthreads();
    if (t < NH) {
        float s = 0.f;
        for (int j = 0; j < HDm; j++) s += sh[t*HDm + ((j + t) & 63)];
        hs[t] = s;
    }
    __syncthreads();
    if (t == 0) {
        float s2 = 0.f;
        #pragma unroll
        for (int h = 0; h < NH; h++) s2 += hs[h];
        float ls = (w==0) ? lsq[0] : ((w==1) ? lsk[0] : lsv[0]);
        float y0 = y[0];
        float time = expf(ls) / (1.f + expf(-y0)) + 1.1f;
        float sc = (time*time - 1.f) / fmaxf(s2, EPSF);
        bc[0] = sc;
        bc[1] = sqrtf(sc);
    }
    __syncthreads();
    const float sc = bc[0], ss = bc[1];
    const int b = m >> 10, tt = m & 1023;
    float* base = g_qkv[w];
    #pragma unroll
    for (int i = 0; i < 4; i++) {
        int j = t + (i << 8);
        int h = j >> 6, d = j & 63;
        base[((size_t)(b*NH + h)*TT + tt)*(HDm+1) + 1 + d] = ss * v[i];
    }
    if (t < NH)
        base[((size_t)(b*NH + t)*TT + tt)*(HDm+1)] = sqrtf(sc * hs[t] + 1.f);
}

// ---------------------------------------------------------------------------
// Flash attention + Lorentz centroid on TF32 tensor cores.
// 64 q-rows/block, 64-key tiles, 8 warps.
// ---------------------------------------------------------------------------
#define QP 76   // Q/K smem pitch (words)
#define SP 68   // S/P smem pitch
#define VP 76   // V^T smem pitch
#define OPit 84 // O epilogue pitch

__global__ __launch_bounds__(256) void attn_mma_k(const float* __restrict__ bias_p)
{
    extern __shared__ float smv[];
    unsigned* Qs = (unsigned*)smv;         // [64][QP]
    unsigned* Ks = Qs + 64*QP;             // [64][QP] (time negated)
    unsigned* Vt = Ks + 64*QP;             // [80][VP]  V^T: [dim][key], tf32
    float* Ss    = (float*)(Vt + 80*VP);   // [64][SP]  scores, then P (tf32 bits)
    float* pmax  = Ss + 64*SP;             // [4][64]
    float* psum  = pmax + 256;             // [4][64]
    float* mrow  = psum + 256;             // [64]
    float* lrow  = mrow + 64;
    float* arow  = lrow + 64;
    float* drow  = arow + 64;
    float* osm   = (float*)Qs;             // [64][OPit] reuse after main loop

    const int t    = threadIdx.x;
    const int lane = t & 31, warp = t >> 5;
    const int g    = lane >> 2, tg = lane & 3;
    const int wm   = (warp >> 1) << 4;     // 0,16,32,48
    const int wn   = (warp & 1) << 5;      // S col band: 0,32
    const int wno  = (warp & 1) * 40;      // O col band: 0,40
    const int bh   = blockIdx.y;
    const int qb   = blockIdx.x << 6;
    const int rq   = t & 63, qd = t >> 6;  // softmax row / quarter

    const float sc1 = 2.f * ATT_SCALE;
    const float sc0 = 2.f * ATT_SCALE + bias_p[0];

    const float* Qg = g_qkv[0] + (size_t)bh * TT * 65;
    const float* Kg = g_qkv[1] + (size_t)bh * TT * 65;
    const float* Vg = g_qkv[2] + (size_t)bh * TT * 65;

    // load Q (tf32, pad cols 65..71 with 0)
    for (int i = t; i < 64*72; i += 256) {
        int r = i / 72, c = i - r*72;
        Qs[r*QP + c] = (c < 65) ? f2tf(Qg[(size_t)(qb + r)*65 + c]) : 0u;
    }
    // zero V^T pad rows 65..79
    for (int i = t; i < 15*64; i += 256) {
        int n = 65 + i/64, k = i & 63;
        Vt[n*VP + k] = 0u;
    }
    if (t < 64) { mrow[t] = -INFINITY; lrow[t] = 0.f; }

    float o[5][4];
    #pragma unroll
    for (int nt = 0; nt < 5; nt++)
        #pragma unroll
        for (int r = 0; r < 4; r++) o[nt][r] = 0.f;
    __syncthreads();

    for (int kb = 0; kb < TT; kb += 64) {
        // load K (negate time, pad) and V^T
        for (int i = t; i < 64*72; i += 256) {
            int r = i / 72, c = i - r*72;
            if (c < 65) {
                float kv = Kg[(size_t)(kb + r)*65 + c];
                Ks[r*QP + c] = f2tf((c == 0) ? -kv : kv);
                Vt[c*VP + r] = f2tf(Vg[(size_t)(kb + r)*65 + c]);
            } else {
                Ks[r*QP + c] = 0u;
            }
        }
        __syncthreads();

        // S = Q K'^T  (16x32 per warp, k=72)
        float sf[4][4];
        #pragma unroll
        for (int nj = 0; nj < 4; nj++)
            #pragma unroll
            for (int r = 0; r < 4; r++) sf[nj][r] = 0.f;
        #pragma unroll
        for (int ks = 0; ks < 9; ks++) {
            const int kc = ks << 3;
            unsigned a0 = Qs[(wm+g  )*QP + kc + tg];
            unsigned a1 = Qs[(wm+g+8)*QP + kc + tg];
            unsigned a2 = Qs[(wm+g  )*QP + kc + tg + 4];
            unsigned a3 = Qs[(wm+g+8)*QP + kc + tg + 4];
            #pragma unroll
            for (int nj = 0; nj < 4; nj++) {
                int col = wn + (nj << 3) + g;
                unsigned b0 = Ks[col*QP + kc + tg];
                unsigned b1 = Ks[col*QP + kc + tg + 4];
                MMA_TF32(sf[nj][0], sf[nj][1], sf[nj][2], sf[nj][3],
                         a0, a1, a2, a3, b0, b1);
            }
        }
        // affine + store scores
        #pragma unroll
        for (int nj = 0; nj < 4; nj++) {
            int cb = wn + (nj << 3) + (tg << 1);
            Ss[(wm+g  )*SP + cb    ] = fmaf(sf[nj][0], sc1, sc0);
            Ss[(wm+g  )*SP + cb + 1] = fmaf(sf[nj][1], sc1, sc0);
            Ss[(wm+g+8)*SP + cb    ] = fmaf(sf[nj][2], sc1, sc0);
            Ss[(wm+g+8)*SP + cb + 1] = fmaf(sf[nj][3], sc1, sc0);
        }
        __syncthreads();

        // row max partials (each thread: one row-quarter)
        {
            float mx = -INFINITY;
            #pragma unroll
            for (int j = 0; j < 16; j++)
                mx = fmaxf(mx, Ss[rq*SP + (qd<<4) + j]);
            pmax[(qd<<6) + rq] = mx;
        }
        __syncthreads();
        if (t < 64) {
            float mold = mrow[t];
            float mn = fmaxf(fmaxf(fmaxf(pmax[t], pmax[64+t]), pmax[128+t]), fmaxf(pmax[192+t], mold));
            float al = __expf(mold - mn);
            mrow[t] = mn; arow[t] = al; lrow[t] *= al;
        }
        __syncthreads();

        // exp -> P (tf32 bits), partial sums from converted values
        {
            float ml = mrow[rq];
            float s = 0.f;
            #pragma unroll
            for (int j = 0; j < 16; j++) {
                float p = __expf(Ss[rq*SP + (qd<<4) + j] - ml);
                unsigned pt = f2tf(p);
                Ss[rq*SP + (qd<<4) + j] = __uint_as_float(pt);
                s += __uint_as_float(pt);
            }
            psum[(qd<<6) + rq] = s;
        }
        __syncthreads();
        if (t < 64)
            lrow[t] += psum[t] + psum[64+t] + psum[128+t] + psum[192+t];

        // rescale O, then O += P V  (16x40 per warp, k=64)
        {
            float al0 = arow[wm+g], al1 = arow[wm+g+8];
            #pragma unroll
            for (int nt = 0; nt < 5; nt++) {
                o[nt][0] *= al0; o[nt][1] *= al0;
                o[nt][2] *= al1; o[nt][3] *= al1;
            }
        }
        const unsigned* Pu = (const unsigned*)Ss;
        #pragma unroll
        for (int ks = 0; ks < 8; ks++) {
            const int kc = ks << 3;
            unsigned a0 = Pu[(wm+g  )*SP + kc + tg];
            unsigned a1 = Pu[(wm+g+8)*SP + kc + tg];
            unsigned a2 = Pu[(wm+g  )*SP + kc + tg + 4];
            unsigned a3 = Pu[(wm+g+8)*SP + kc + tg + 4];
            #pragma unroll
            for (int nt = 0; nt < 5; nt++) {
                int col = wno + (nt << 3) + g;
                unsigned b0 = Vt[col*VP + kc + tg];
                unsigned b1 = Vt[col*VP + kc + tg + 4];
                MMA_TF32(o[nt][0], o[nt][1], o[nt][2], o[nt][3],
                         a0, a1, a2, a3, b0, b1);
            }
        }
        __syncthreads();
    }

    // epilogue: divide by l, stash to osm (reuses Q/K smem)
    {
        float il0 = 1.f / lrow[wm+g], il1 = 1.f / lrow[wm+g+8];
        #pragma unroll
        for (int nt = 0; nt < 5; nt++) {
            int cb = wno + (nt << 3) + (tg << 1);
            osm[(wm+g  )*OPit + cb    ] = o[nt][0] * il0;
            osm[(wm+g  )*OPit + cb + 1] = o[nt][1] * il0;
            osm[(wm+g+8)*OPit + cb    ] = o[nt][2] * il1;
            osm[(wm+g+8)*OPit + cb + 1] = o[nt][3] * il1;
        }
    }
    __syncthreads();
    // centroid normalization: ssq over space dims (cols 1..64)
    {
        float s = 0.f;
        #pragma unroll
        for (int j = 0; j < 16; j++) {
            float x = osm[rq*OPit + 1 + (qd<<4) + j];
            s = fmaf(x, x, s);
        }
        psum[(qd<<6) + rq] = s;
    }
    __syncthreads();
    if (t < 64) {
        float s = psum[t] + psum[64+t] + psum[128+t] + psum[192+t];
        float tav = osm[t*OPit];
        float ni = tav*tav - s;
        drow[t] = 1.f / sqrtf(fmaxf(fabsf(ni), EPSF));
    }
    __syncthreads();

    const int b = bh >> 4, h = bh & 15;
    {
        float dv = drow[rq];
        float* dst = g_ao + ((size_t)(b*TT) + qb + rq)*DD + 1 + h*64 + (qd<<4);
        #pragma unroll
        for (int j = 0; j < 16; j++)
            dst[j] = osm[rq*OPit + 1 + (qd<<4) + j] * dv;
    }
}

// ---------------------------------------------------------------------------
// Global add_time for attention output rows
// ---------------------------------------------------------------------------
__global__ __launch_bounds__(256) void ao_time_k()
{
    const int m = blockIdx.x;
    float* row = g_ao + (size_t)m * DD;
    __shared__ float red[256];
    const int t = threadIdx.x;
    float s = 0.f;
    #pragma unroll
    for (int i = 0; i < 4; i++) {
        float x = row[1 + t + (i << 8)];
        s = fmaf(x, x, s);
    }
    red[t] = s;
    __syncthreads();
    for (int o2 = 128; o2 > 0; o2 >>= 1) {
        if (t < o2) red[t] += red[t + o2];
        __syncthreads();
    }
    if (t == 0) row[0] = sqrtf(red[0] + 1.f);
}

// ---------------------------------------------------------------------------
// Final Lorentz transform -> out
// ---------------------------------------------------------------------------
__global__ __launch_bounds__(256) void transform_final_k(
    const float* __restrict__ lso, float* __restrict__ out)
{
    const int m = blockIdx.x;
    const float* y = g_y[0] + (size_t)m * DD;
    __shared__ float red[256];
    __shared__ float bc[2];
    const int t = threadIdx.x;
    float v[4]; float s = 0.f;
    #pragma unroll
    for (int i = 0; i < 4; i++) {
        v[i] = y[1 + t + (i << 8)];
        s = fmaf(v[i], v[i], s);
    }
    red[t] = s;
    __syncthreads();
    for (int o2 = 128; o2 > 0; o2 >>= 1) {
        if (t < o2) red[t] += red[t + o2];
        __syncthreads();
    }
    if (t == 0) {
        float time = expf(lso[0]) / (1.f + expf(-y[0])) + 1.1f;
        float sc = (time*time - 1.f) / fmaxf(red[0], EPSF);
        bc[0] = time;
        bc[1] = sqrtf(sc);
    }
    __syncthreads();
    const float ss = bc[1];
    float* orow = out + (size_t)m * DD;
    if (t == 0) orow[0] = bc[0];
    #pragma unroll
    for (int i = 0; i < 4; i++) orow[1 + t + (i << 8)] = ss * v[i];
}

// ---------------------------------------------------------------------------
extern "C" void kernel_launch(void* const* d_in, const int* in_sizes, int n_in,
                              void* d_out, int out_size)
{
    const float* hid = (const float*)d_in[0];
    const float* Wq  = (const float*)d_in[1];
    const float* bq  = (const float*)d_in[2];
    const float* sq  = (const float*)d_in[3];
    const float* Wk  = (const float*)d_in[4];
    const float* bk  = (const float*)d_in[5];
    const float* sk  = (const float*)d_in[6];
    const float* Wv  = (const float*)d_in[7];
    const float* bv  = (const float*)d_in[8];
    const float* sv  = (const float*)d_in[9];
    const float* Wo  = (const float*)d_in[10];
    const float* bo  = (const float*)d_in[11];
    const float* so  = (const float*)d_in[12];
    const float* ab  = (const float*)d_in[13];
    float* out = (float*)d_out;

    // attn smem: Qs+Ks (2*64*76) + Vt (80*76) + Ss (64*68) + partials (512) + rows (256)
    static const size_t attn_smem = (size_t)(2*64*QP + 80*VP + 64*SP + 512 + 256) * sizeof(float);
    cudaFuncSetAttribute(attn_mma_k, cudaFuncAttributeMaxDynamicSharedMemorySize, (int)attn_smem);

    gemm_tf32_k<<<dim3(9, 64, 3), 256>>>(hid, Wq, bq, Wk, bk, Wv, bv);
    transform_qkv_k<<<dim3(MM, 3), 256>>>(sq, sk, sv);
    attn_mma_k<<<dim3(TT/64, BHn), 256, attn_smem>>>(ab);
    ao_time_k<<<MM, 256>>>();
    gemm_tf32_k<<<dim3(9, 64, 1), 256>>>(nullptr, Wo, bo, Wo, bo, Wo, bo);
    transform_final_k<<<MM, 256>>>(so, out);
}

// round 7
// speedup vs baseline: 1.6428x; 1.0236x over previous
#include <cuda_runtime.h>
#include <math.h>

// Problem constants
#define NB   8
#define TT   1024
#define EE   1024
#define DD   1025
#define NH   16
#define HDm  64
#define BHn  (NB*NH)      // 128
#define MM   (NB*TT)      // 8192
#define EPSF 1e-8f
#define ATT_SCALE 0.125f  // hd^-0.5

// Scratch (module-scope; no runtime allocation)
__device__ float g_y[3][(size_t)MM*DD];             // linear outputs
__device__ float g_qkv[3][(size_t)BHn*TT*(HDm+1)];  // head-shaped q,k,v [bh][t][65]
__device__ float g_ao[(size_t)MM*DD];               // attention output; col0 = ssq accum

__device__ __forceinline__ unsigned f2tf(float x) {
    unsigned u; asm("cvt.rna.tf32.f32 %0, %1;" : "=r"(u) : "f"(x)); return u;
}

#define MMA_TF32(d0,d1,d2,d3,a0,a1,a2,a3,b0,b1) \
    asm volatile("mma.sync.aligned.m16n8k8.row.col.f32.tf32.tf32.f32 " \
        "{%0,%1,%2,%3}, {%4,%5,%6,%7}, {%8,%9}, {%0,%1,%2,%3};" \
        : "+f"(d0), "+f"(d1), "+f"(d2), "+f"(d3) \
        : "r"(a0), "r"(a1), "r"(a2), "r"(a3), "r"(b0), "r"(b1))

// ---------------------------------------------------------------------------
// TF32 tensor-core GEMM: Y = X W^T + b.
// fuse_time: X col 0 is a raw ssq accumulator -> apply sqrt(v+1) at load.
// ---------------------------------------------------------------------------
#define GP 20

__global__ __launch_bounds__(256, 2) void gemm_tf32_k(
    const float* __restrict__ Xext,
    const float* __restrict__ W0, const float* __restrict__ B0,
    const float* __restrict__ W1, const float* __restrict__ B1,
    const float* __restrict__ W2, const float* __restrict__ B2,
    int fuse_time)
{
    const int w = blockIdx.z;
    const float* X  = Xext ? Xext : g_ao;
    const float* Wp = (w==0) ? W0 : ((w==1) ? W1 : W2);
    const float* Bp = (w==0) ? B0 : ((w==1) ? B1 : B2);
    float* Y = g_y[w];

    __shared__ unsigned As[128][GP];
    __shared__ unsigned Bs[128][GP];

    const int t    = threadIdx.x;
    const int lane = t & 31;
    const int warp = t >> 5;
    const int g    = lane >> 2;
    const int tg   = lane & 3;
    const int wm   = (warp & 1) << 6;
    const int wn   = (warp >> 1) << 5;
    const int bm   = blockIdx.y << 7;
    const int bn   = blockIdx.x << 7;

    const int sr = t >> 2;
    const int sc = (t & 3) << 2;

    const float* xr0 = X + (size_t)(bm + sr) * DD;
    const float* xr1 = X + (size_t)(bm + sr + 64) * DD;
    const int n0 = bn + sr, n1 = bn + sr + 64;
    const bool n0ok = (n0 < DD), n1ok = (n1 < DD);
    const float* wr0 = Wp + (size_t)(n0ok ? n0 : 0) * DD;
    const float* wr1 = Wp + (size_t)(n1ok ? n1 : 0) * DD;

    float acc[4][4][4];
    #pragma unroll
    for (int i = 0; i < 4; i++)
        #pragma unroll
        for (int j = 0; j < 4; j++)
            #pragma unroll
            for (int r = 0; r < 4; r++) acc[i][j][r] = 0.f;

    float rA[8], rB[8];
    #pragma unroll
    for (int i = 0; i < 4; i++) {
        float v0 = xr0[sc + i];
        float v1 = xr1[sc + i];
        if (fuse_time && (sc + i) == 0) {   // global col 0: time = sqrt(ssq+1)
            v0 = sqrtf(v0 + 1.f);
            v1 = sqrtf(v1 + 1.f);
        }
        rA[i]   = v0;
        rA[4+i] = v1;
        rB[i]   = n0ok ? wr0[sc + i] : 0.f;
        rB[4+i] = n1ok ? wr1[sc + i] : 0.f;
    }

    for (int k0 = 0; k0 < DD; k0 += 16) {
        *(uint4*)&As[sr][sc]      = make_uint4(f2tf(rA[0]), f2tf(rA[1]), f2tf(rA[2]), f2tf(rA[3]));
        *(uint4*)&As[sr + 64][sc] = make_uint4(f2tf(rA[4]), f2tf(rA[5]), f2tf(rA[6]), f2tf(rA[7]));
        *(uint4*)&Bs[sr][sc]      = make_uint4(f2tf(rB[0]), f2tf(rB[1]), f2tf(rB[2]), f2tf(rB[3]));
        *(uint4*)&Bs[sr + 64][sc] = make_uint4(f2tf(rB[4]), f2tf(rB[5]), f2tf(rB[6]), f2tf(rB[7]));
        __syncthreads();

        const int kn = k0 + 16;
        if (kn < DD) {
            #pragma unroll
            for (int i = 0; i < 4; i++) {
                int k = kn + sc + i;
                bool kok = (k < DD);
                rA[i]   = kok ? xr0[k] : 0.f;
                rA[4+i] = kok ? xr1[k] : 0.f;
                rB[i]   = (kok && n0ok) ? wr0[k] : 0.f;
                rB[4+i] = (kok && n1ok) ? wr1[k] : 0.f;
            }
        }

        #pragma unroll
        for (int ks = 0; ks < 16; ks += 8) {
            unsigned a[4][4], b[4][2];
            #pragma unroll
            for (int mi = 0; mi < 4; mi++) {
                int row = wm + (mi << 4) + g;
                a[mi][0] = As[row    ][ks + tg];
                a[mi][1] = As[row + 8][ks + tg];
                a[mi][2] = As[row    ][ks + tg + 4];
                a[mi][3] = As[row + 8][ks + tg + 4];
            }
            #pragma unroll
            for (int nj = 0; nj < 4; nj++) {
                int col = wn + (nj << 3) + g;
                b[nj][0] = Bs[col][ks + tg];
                b[nj][1] = Bs[col][ks + tg + 4];
            }
            #pragma unroll
            for (int mi = 0; mi < 4; mi++)
                #pragma unroll
                for (int nj = 0; nj < 4; nj++)
                    MMA_TF32(acc[mi][nj][0], acc[mi][nj][1], acc[mi][nj][2], acc[mi][nj][3],
                             a[mi][0], a[mi][1], a[mi][2], a[mi][3], b[nj][0], b[nj][1]);
        }
        __syncthreads();
    }

    #pragma unroll
    for (int mi = 0; mi < 4; mi++) {
        int row = bm + wm + (mi << 4) + g;
        float* yr0 = Y + (size_t)row * DD;
        float* yr1 = Y + (size_t)(row + 8) * DD;
        #pragma unroll
        for (int nj = 0; nj < 4; nj++) {
            int col = bn + wn + (nj << 3) + (tg << 1);
            if (col < DD) {
                float bb = Bp[col];
                yr0[col] = acc[mi][nj][0] + bb;
                yr1[col] = acc[mi][nj][2] + bb;
            }
            if (col + 1 < DD) {
                float bb = Bp[col + 1];
                yr0[col + 1] = acc[mi][nj][1] + bb;
                yr1[col + 1] = acc[mi][nj][3] + bb;
            }
        }
    }
}

// ---------------------------------------------------------------------------
// Lorentz transform + head-shaping for q/k/v. Also zeroes g_ao col 0 (ssq acc).
// ---------------------------------------------------------------------------
__global__ __launch_bounds__(256) void transform_qkv_k(
    const float* __restrict__ lsq, const float* __restrict__ lsk,
    const float* __restrict__ lsv)
{
    const int m = blockIdx.x, w = blockIdx.y;
    const float* y = g_y[w] + (size_t)m * DD;
    __shared__ float sh[EE];
    __shared__ float hs[NH];
    __shared__ float bc[2];
    const int t = threadIdx.x;

    if (w == 0 && t == 0) g_ao[(size_t)m * DD] = 0.f;  // reset ssq accumulator

    float v[4];
    #pragma unroll
    for (int i = 0; i < 4; i++) {
        int j = t + (i << 8);
        v[i] = y[1 + j];
        sh[j] = v[i] * v[i];
    }
    __syncthreads();
    if (t < NH) {
        float s = 0.f;
        for (int j = 0; j < HDm; j++) s += sh[t*HDm + ((j + t) & 63)];
        hs[t] = s;
    }
    __syncthreads();
    if (t == 0) {
        float s2 = 0.f;
        #pragma unroll
        for (int h = 0; h < NH; h++) s2 += hs[h];
        float ls = (w==0) ? lsq[0] : ((w==1) ? lsk[0] : lsv[0]);
        float y0 = y[0];
        float time = expf(ls) / (1.f + expf(-y0)) + 1.1f;
        float sc = (time*time - 1.f) / fmaxf(s2, EPSF);
        bc[0] = sc;
        bc[1] = sqrtf(sc);
    }
    __syncthreads();
    const float sc = bc[0], ss = bc[1];
    const int b = m >> 10, tt = m & 1023;
    float* base = g_qkv[w];
    #pragma unroll
    for (int i = 0; i < 4; i++) {
        int j = t + (i << 8);
        int h = j >> 6, d = j & 63;
        base[((size_t)(b*NH + h)*TT + tt)*(HDm+1) + 1 + d] = ss * v[i];
    }
    if (t < NH)
        base[((size_t)(b*NH + t)*TT + tt)*(HDm+1)] = sqrtf(sc * hs[t] + 1.f);
}

// ---------------------------------------------------------------------------
// Flash attention + Lorentz centroid, TF32 MMA, register-resident softmax.
// ---------------------------------------------------------------------------
#define QP 76   // Q/K smem pitch (words)
#define SP 68   // P smem pitch (A-frag loads conflict-free; stores 2-way)
#define VP 76   // V^T smem pitch
#define OPit 85 // O epilogue pitch (odd -> row scans conflict-free)

__global__ __launch_bounds__(256) void attn_mma_k(const float* __restrict__ bias_p)
{
    extern __shared__ float smv[];
    unsigned* Qs = (unsigned*)smv;         // [64][QP]
    unsigned* Ks = Qs + 64*QP;             // [64][QP] (time negated)
    unsigned* Vt = Ks + 64*QP;             // [80][VP]  V^T: [dim][key], tf32
    unsigned* Ps = Vt + 80*VP;             // [64][SP]  P (tf32 bits)
    float* bmax  = (float*)(Ps + 64*SP);   // [2][64] band max
    float* bsum  = bmax + 128;             // [2][64] band sum
    float* mrow  = bsum + 128;             // [64]
    float* lrow  = mrow + 64;
    float* drow  = lrow + 64;
    float* osm   = (float*)Qs;             // [64][OPit] reuse after main loop

    const int t    = threadIdx.x;
    const int lane = t & 31, warp = t >> 5;
    const int g    = lane >> 2, tg = lane & 3;
    const int wh   = warp & 1;             // warp half (col band)
    const int wm   = (warp >> 1) << 4;     // 0,16,32,48
    const int wn   = wh << 5;              // S col band: 0,32
    const int wno  = wh * 40;              // O col band: 0,40
    const int bh   = blockIdx.y;
    const int qb   = blockIdx.x << 6;
    const int rq   = t & 63, qd = t >> 6;  // epilogue row / quarter
    const int r0   = wm + g, r1 = wm + g + 8;

    const float sc1 = 2.f * ATT_SCALE;
    const float sc0 = 2.f * ATT_SCALE + bias_p[0];

    const float* Qg = g_qkv[0] + (size_t)bh * TT * 65;
    const float* Kg = g_qkv[1] + (size_t)bh * TT * 65;
    const float* Vg = g_qkv[2] + (size_t)bh * TT * 65;

    // load Q (tf32, pad cols 65..71 with 0)
    for (int i = t; i < 64*72; i += 256) {
        int r = i / 72, c = i - r*72;
        Qs[r*QP + c] = (c < 65) ? f2tf(Qg[(size_t)(qb + r)*65 + c]) : 0u;
    }
    // zero V^T pad rows 65..79
    for (int i = t; i < 15*64; i += 256) {
        int n = 65 + i/64, k = i & 63;
        Vt[n*VP + k] = 0u;
    }
    if (t < 64) { mrow[t] = -INFINITY; lrow[t] = 0.f; }

    float o[5][4];
    #pragma unroll
    for (int nt = 0; nt < 5; nt++)
        #pragma unroll
        for (int r = 0; r < 4; r++) o[nt][r] = 0.f;
    __syncthreads();

    for (int kb = 0; kb < TT; kb += 64) {
        // load K (negate time, pad) and V^T
        for (int i = t; i < 64*72; i += 256) {
            int r = i / 72, c = i - r*72;
            if (c < 65) {
                float kv = Kg[(size_t)(kb + r)*65 + c];
                Ks[r*QP + c] = f2tf((c == 0) ? -kv : kv);
                Vt[c*VP + r] = f2tf(Vg[(size_t)(kb + r)*65 + c]);
            } else {
                Ks[r*QP + c] = 0u;
            }
        }
        __syncthreads();

        // S = Q K'^T  (16x32 per warp, k=72), affine in-register
        float sf[4][4];
        #pragma unroll
        for (int nj = 0; nj < 4; nj++)
            #pragma unroll
            for (int r = 0; r < 4; r++) sf[nj][r] = 0.f;
        #pragma unroll
        for (int ks = 0; ks < 9; ks++) {
            const int kc = ks << 3;
            unsigned a0 = Qs[r0*QP + kc + tg];
            unsigned a1 = Qs[r1*QP + kc + tg];
            unsigned a2 = Qs[r0*QP + kc + tg + 4];
            unsigned a3 = Qs[r1*QP + kc + tg + 4];
            #pragma unroll
            for (int nj = 0; nj < 4; nj++) {
                int col = wn + (nj << 3) + g;
                unsigned b0 = Ks[col*QP + kc + tg];
                unsigned b1 = Ks[col*QP + kc + tg + 4];
                MMA_TF32(sf[nj][0], sf[nj][1], sf[nj][2], sf[nj][3],
                         a0, a1, a2, a3, b0, b1);
            }
        }
        float mx0 = -INFINITY, mx1 = -INFINITY;
        #pragma unroll
        for (int nj = 0; nj < 4; nj++) {
            sf[nj][0] = fmaf(sf[nj][0], sc1, sc0);
            sf[nj][1] = fmaf(sf[nj][1], sc1, sc0);
            sf[nj][2] = fmaf(sf[nj][2], sc1, sc0);
            sf[nj][3] = fmaf(sf[nj][3], sc1, sc0);
            mx0 = fmaxf(mx0, fmaxf(sf[nj][0], sf[nj][1]));
            mx1 = fmaxf(mx1, fmaxf(sf[nj][2], sf[nj][3]));
        }
        // quad reduce (lanes 4g..4g+3)
        mx0 = fmaxf(mx0, __shfl_xor_sync(0xFFFFFFFFu, mx0, 1));
        mx0 = fmaxf(mx0, __shfl_xor_sync(0xFFFFFFFFu, mx0, 2));
        mx1 = fmaxf(mx1, __shfl_xor_sync(0xFFFFFFFFu, mx1, 1));
        mx1 = fmaxf(mx1, __shfl_xor_sync(0xFFFFFFFFu, mx1, 2));
        if (tg == 0) { bmax[wh*64 + r0] = mx0; bmax[wh*64 + r1] = mx1; }
        __syncthreads();

        const float mold0 = mrow[r0], mold1 = mrow[r1];
        const float mn0 = fmaxf(mold0, fmaxf(bmax[r0], bmax[64 + r0]));
        const float mn1 = fmaxf(mold1, fmaxf(bmax[r1], bmax[64 + r1]));
        const float al0 = __expf(mold0 - mn0);
        const float al1 = __expf(mold1 - mn1);

        // exp in-register -> P tf32 to smem; band sums from converted values
        float s0 = 0.f, s1 = 0.f;
        #pragma unroll
        for (int nj = 0; nj < 4; nj++) {
            int cb = wn + (nj << 3) + (tg << 1);
            unsigned p00 = f2tf(__expf(sf[nj][0] - mn0));
            unsigned p01 = f2tf(__expf(sf[nj][1] - mn0));
            unsigned p10 = f2tf(__expf(sf[nj][2] - mn1));
            unsigned p11 = f2tf(__expf(sf[nj][3] - mn1));
            Ps[r0*SP + cb] = p00; Ps[r0*SP + cb + 1] = p01;
            Ps[r1*SP + cb] = p10; Ps[r1*SP + cb + 1] = p11;
            s0 += __uint_as_float(p00) + __uint_as_float(p01);
            s1 += __uint_as_float(p10) + __uint_as_float(p11);
        }
        s0 += __shfl_xor_sync(0xFFFFFFFFu, s0, 1);
        s0 += __shfl_xor_sync(0xFFFFFFFFu, s0, 2);
        s1 += __shfl_xor_sync(0xFFFFFFFFu, s1, 1);
        s1 += __shfl_xor_sync(0xFFFFFFFFu, s1, 2);
        if (tg == 0) { bsum[wh*64 + r0] = s0; bsum[wh*64 + r1] = s1; }

        // rescale O
        #pragma unroll
        for (int nt = 0; nt < 5; nt++) {
            o[nt][0] *= al0; o[nt][1] *= al0;
            o[nt][2] *= al1; o[nt][3] *= al1;
        }
        __syncthreads();

        // designated lanes update running stats (reads of old mrow all done)
        if (wh == 0 && tg == 0) {
            lrow[r0] = lrow[r0]*al0 + bsum[r0] + bsum[64 + r0];
            lrow[r1] = lrow[r1]*al1 + bsum[r1] + bsum[64 + r1];
            mrow[r0] = mn0; mrow[r1] = mn1;
        }

        // O += P V  (16x40 per warp, k=64)
        #pragma unroll
        for (int ks = 0; ks < 8; ks++) {
            const int kc = ks << 3;
            unsigned a0 = Ps[r0*SP + kc + tg];
            unsigned a1 = Ps[r1*SP + kc + tg];
            unsigned a2 = Ps[r0*SP + kc + tg + 4];
            unsigned a3 = Ps[r1*SP + kc + tg + 4];
            #pragma unroll
            for (int nt = 0; nt < 5; nt++) {
                int col = wno + (nt << 3) + g;
                unsigned b0 = Vt[col*VP + kc + tg];
                unsigned b1 = Vt[col*VP + kc + tg + 4];
                MMA_TF32(o[nt][0], o[nt][1], o[nt][2], o[nt][3],
                         a0, a1, a2, a3, b0, b1);
            }
        }
        __syncthreads();
    }

    // epilogue: divide by l, stash to osm (reuses Q/K smem region)
    {
        float il0 = 1.f / lrow[r0], il1 = 1.f / lrow[r1];
        #pragma unroll
        for (int nt = 0; nt < 5; nt++) {
            int cb = wno + (nt << 3) + (tg << 1);
            osm[r0*OPit + cb    ] = o[nt][0] * il0;
            osm[r0*OPit + cb + 1] = o[nt][1] * il0;
            osm[r1*OPit + cb    ] = o[nt][2] * il1;
            osm[r1*OPit + cb + 1] = o[nt][3] * il1;
        }
    }
    __syncthreads();
    // centroid normalization: ssq over space dims (cols 1..64)
    {
        float s = 0.f;
        #pragma unroll
        for (int j = 0; j < 16; j++) {
            float x = osm[rq*OPit + 1 + (qd<<4) + j];
            s = fmaf(x, x, s);
        }
        bsum[(qd<<6) + rq] = s;   // reuse bmax/bsum region: [4][64] fits in 256
    }
    __syncthreads();
    const int b = bh >> 4, h = bh & 15;
    if (t < 64) {
        float s = bsum[t] + bsum[64+t] + bsum[128+t] + bsum[192+t];
        float tav = osm[t*OPit];
        float ni = tav*tav - s;
        float dv = 1.f / sqrtf(fmaxf(fabsf(ni), EPSF));
        drow[t] = dv;
        // fused ao_time: accumulate this head's normalized ssq into g_ao col 0
        atomicAdd(&g_ao[((size_t)(b*TT) + qb + t)*DD], s * dv * dv);
    }
    __syncthreads();

    {
        float dv = drow[rq];
        float* dst = g_ao + ((size_t)(b*TT) + qb + rq)*DD + 1 + h*64 + (qd<<4);
        #pragma unroll
        for (int j = 0; j < 16; j++)
            dst[j] = osm[rq*OPit + 1 + (qd<<4) + j] * dv;
    }
}

// ---------------------------------------------------------------------------
// Final Lorentz transform -> out
// ---------------------------------------------------------------------------
__global__ __launch_bounds__(256) void transform_final_k(
    const float* __restrict__ lso, float* __restrict__ out)
{
    const int m = blockIdx.x;
    const float* y = g_y[0] + (size_t)m * DD;
    __shared__ float red[256];
    __shared__ float bc[2];
    const int t = threadIdx.x;
    float v[4]; float s = 0.f;
    #pragma unroll
    for (int i = 0; i < 4; i++) {
        v[i] = y[1 + t + (i << 8)];
        s = fmaf(v[i], v[i], s);
    }
    red[t] = s;
    __syncthreads();
    for (int o2 = 128; o2 > 0; o2 >>= 1) {
        if (t < o2) red[t] += red[t + o2];
        __syncthreads();
    }
    if (t == 0) {
        float time = expf(lso[0]) / (1.f + expf(-y[0])) + 1.1f;
        float sc = (time*time - 1.f) / fmaxf(red[0], EPSF);
        bc[0] = time;
        bc[1] = sqrtf(sc);
    }
    __syncthreads();
    const float ss = bc[1];
    float* orow = out + (size_t)m * DD;
    if (t == 0) orow[0] = bc[0];
    #pragma unroll
    for (int i = 0; i < 4; i++) orow[1 + t + (i << 8)] = ss * v[i];
}

// ---------------------------------------------------------------------------
extern "C" void kernel_launch(void* const* d_in, const int* in_sizes, int n_in,
                              void* d_out, int out_size)
{
    const float* hid = (const float*)d_in[0];
    const float* Wq  = (const float*)d_in[1];
    const float* bq  = (const float*)d_in[2];
    const float* sq  = (const float*)d_in[3];
    const float* Wk  = (const float*)d_in[4];
    const float* bk  = (const float*)d_in[5];
    const float* sk  = (const float*)d_in[6];
    const float* Wv  = (const float*)d_in[7];
    const float* bv  = (const float*)d_in[8];
    const float* sv  = (const float*)d_in[9];
    const float* Wo  = (const float*)d_in[10];
    const float* bo  = (const float*)d_in[11];
    const float* so  = (const float*)d_in[12];
    const float* ab  = (const float*)d_in[13];
    float* out = (float*)d_out;

    // attn smem: Qs+Ks (2*64*76) + Vt (80*76) + Ps (64*68) + bmax/bsum (256) + rows (192)
    static const size_t attn_smem = (size_t)(2*64*QP + 80*VP + 64*SP + 256 + 192) * sizeof(float);
    cudaFuncSetAttribute(attn_mma_k, cudaFuncAttributeMaxDynamicSharedMemorySize, (int)attn_smem);

    gemm_tf32_k<<<dim3(9, 64, 3), 256>>>(hid, Wq, bq, Wk, bk, Wv, bv, 0);   // 0
    transform_qkv_k<<<dim3(MM, 3), 256>>>(sq, sk, sv);                       // 1
    attn_mma_k<<<dim3(TT/64, BHn), 256, attn_smem>>>(ab);                    // 2
    gemm_tf32_k<<<dim3(9, 64, 1), 256>>>(nullptr, Wo, bo, Wo, bo, Wo, bo, 1);// 3 (profiled)
    transform_final_k<<<MM, 256>>>(so, out);                                 // 4
}